// round 1
// baseline (speedup 1.0000x reference)
#include <cuda_runtime.h>
#include <math.h>

// ---------------------------------------------------------------------------
// Problem constants (fixed shapes per reference)
// ---------------------------------------------------------------------------
#define N_USERS 100000
#define N_ITEMS 50000
#define DIM     128
#define E_U     400000
#define E_I     200000
#define BATCH   4096

// ---------------------------------------------------------------------------
// Device scratch (static — no allocations allowed)
// ---------------------------------------------------------------------------
__device__ float g_h[N_USERS * DIM];          // shared h buffer (max size)
__device__ float g_out_u1[N_USERS * DIM];
__device__ float g_out_u2[N_USERS * DIM];
__device__ float g_out_i1[N_ITEMS * DIM];
__device__ float g_out_i2[N_ITEMS * DIM];
__device__ float g_as[N_USERS];
__device__ float g_ad[N_USERS];
__device__ int   g_rowptr_u[N_USERS + 1];
__device__ int   g_rowptr_i[N_ITEMS + 1];
__device__ int   g_counts[N_USERS];
__device__ int   g_cursor[N_USERS];
__device__ int   g_srcS_u[E_U];
__device__ int   g_dstS_u[E_U];
__device__ float g_valS_u[E_U];
__device__ int   g_srcS_i[E_I];
__device__ int   g_dstS_i[E_I];
__device__ float g_valS_i[E_I];
__device__ float g_logitS[E_U];               // shared (max size)

// ---------------------------------------------------------------------------
// CSR build: histogram -> single-block scan -> scatter
// ---------------------------------------------------------------------------
__global__ void zero2_kernel(int* a, int* b, int n) {
    int i = blockIdx.x * blockDim.x + threadIdx.x;
    if (i < n) { a[i] = 0; b[i] = 0; }
}

__global__ void hist_kernel(const int* __restrict__ dst, int* counts, int E) {
    int e = blockIdx.x * blockDim.x + threadIdx.x;
    if (e < E) atomicAdd(&counts[dst[e]], 1);
}

// Single-block exclusive scan over counts[n] -> rowptr[n+1]
__global__ void scan_kernel(const int* __restrict__ counts, int* __restrict__ rowptr, int n) {
    __shared__ int ssum[1024];
    int t = threadIdx.x;
    int chunk = (n + 1023) / 1024;
    int lo = t * chunk;
    int hi = min(lo + chunk, n);
    int s = 0;
    for (int i = lo; i < hi; i++) s += counts[i];
    ssum[t] = s;
    __syncthreads();
    // Hillis-Steele inclusive scan over 1024 partials
    for (int o = 1; o < 1024; o <<= 1) {
        int v = (t >= o) ? ssum[t - o] : 0;
        __syncthreads();
        ssum[t] += v;
        __syncthreads();
    }
    int run = (t > 0) ? ssum[t - 1] : 0;
    for (int i = lo; i < hi; i++) { rowptr[i] = run; run += counts[i]; }
    if (t == 0) rowptr[n] = ssum[1023];
}

__global__ void scatter_kernel(const int* __restrict__ src, const int* __restrict__ dst,
                               const float* __restrict__ val,
                               const int* __restrict__ rowptr, int* cursor,
                               int* srcS, int* dstS, float* valS, int E) {
    int e = blockIdx.x * blockDim.x + threadIdx.x;
    if (e >= E) return;
    int d = dst[e];
    int pos = rowptr[d] + atomicAdd(&cursor[d], 1);
    srcS[pos] = src[e];
    dstS[pos] = d;
    valS[pos] = val[e];
}

// ---------------------------------------------------------------------------
// GEMM: H[n][128] = elu?(X)[n][128] @ W[128][128]
// Block: 256 threads, 64 rows per block, K chunks of 32. Each thread: 4x8 accs.
// ---------------------------------------------------------------------------
template <bool ELU_IN>
__global__ void gemm_128_kernel(const float* __restrict__ X, const float* __restrict__ W,
                                float* __restrict__ H, int n) {
    __shared__ float xs[64][33];   // +1 pad: column reads hit distinct banks
    __shared__ float ws[32][128];
    int tx = threadIdx.x & 15;
    int ty = threadIdx.x >> 4;
    int row0 = blockIdx.x * 64;

    float acc[4][8];
#pragma unroll
    for (int i = 0; i < 4; i++)
#pragma unroll
        for (int j = 0; j < 8; j++) acc[i][j] = 0.f;

    for (int k0 = 0; k0 < DIM; k0 += 32) {
        // load X tile (64 x 32)
        for (int i = threadIdx.x; i < 64 * 32; i += 256) {
            int r = i >> 5, c = i & 31;
            int gr = row0 + r;
            float v = (gr < n) ? X[(size_t)gr * DIM + k0 + c] : 0.f;
            if (ELU_IN) v = (v > 0.f) ? v : (expf(v) - 1.f);
            xs[r][c] = v;
        }
        // load W tile (32 x 128)
        for (int i = threadIdx.x; i < 32 * 128; i += 256) {
            int r = i >> 7, c = i & 127;
            ws[r][c] = W[(size_t)(k0 + r) * DIM + c];
        }
        __syncthreads();
#pragma unroll
        for (int kk = 0; kk < 32; kk++) {
            float a[4], b[8];
#pragma unroll
            for (int i = 0; i < 4; i++) a[i] = xs[ty + 16 * i][kk];
#pragma unroll
            for (int j = 0; j < 8; j++) b[j] = ws[kk][tx + 16 * j];
#pragma unroll
            for (int i = 0; i < 4; i++)
#pragma unroll
                for (int j = 0; j < 8; j++) acc[i][j] = fmaf(a[i], b[j], acc[i][j]);
        }
        __syncthreads();
    }
#pragma unroll
    for (int i = 0; i < 4; i++) {
        int gr = row0 + ty + 16 * i;
        if (gr < n) {
#pragma unroll
            for (int j = 0; j < 8; j++)
                H[(size_t)gr * DIM + tx + 16 * j] = acc[i][j];
        }
    }
}

// ---------------------------------------------------------------------------
// Per-node attention dots: alpha_src[n] = h[n]·a_src ; alpha_dst[n] = h[n]·a_dst
// One warp per node.
// ---------------------------------------------------------------------------
__global__ void alpha_kernel(const float* __restrict__ H,
                             const float* __restrict__ a_src, const float* __restrict__ a_dst,
                             float* __restrict__ as, float* __restrict__ ad, int n) {
    int warp = (blockIdx.x * blockDim.x + threadIdx.x) >> 5;
    int lane = threadIdx.x & 31;
    if (warp >= n) return;
    const float* hrow = H + (size_t)warp * DIM;
    float s1 = 0.f, s2 = 0.f;
#pragma unroll
    for (int r = 0; r < 4; r++) {
        float h = hrow[lane + 32 * r];
        s1 = fmaf(h, a_src[lane + 32 * r], s1);
        s2 = fmaf(h, a_dst[lane + 32 * r], s2);
    }
#pragma unroll
    for (int o = 16; o > 0; o >>= 1) {
        s1 += __shfl_xor_sync(0xFFFFFFFFu, s1, o);
        s2 += __shfl_xor_sync(0xFFFFFFFFu, s2, o);
    }
    if (lane == 0) { as[warp] = s1; ad[warp] = s2; }
}

// ---------------------------------------------------------------------------
// Per-edge logits (CSR order): leaky_relu(alpha_src[src] + alpha_dst[dst], 0.2)
// ---------------------------------------------------------------------------
__global__ void logit_kernel(const int* __restrict__ srcS, const int* __restrict__ dstS,
                             const float* __restrict__ as, const float* __restrict__ ad,
                             float* __restrict__ logitS, int E) {
    int e = blockIdx.x * blockDim.x + threadIdx.x;
    if (e >= E) return;
    float l = as[srcS[e]] + ad[dstS[e]];
    logitS[e] = (l >= 0.f) ? l : 0.2f * l;
}

// ---------------------------------------------------------------------------
// Fused neighbor softmax + aggregation: one warp per destination node.
// No atomics; h[src] rows are L2-resident.
// ---------------------------------------------------------------------------
__global__ void aggregate_kernel(const int* __restrict__ rowptr, const int* __restrict__ srcS,
                                 const float* __restrict__ valS, const float* __restrict__ logitS,
                                 const float* __restrict__ H, float* __restrict__ OUT, int n) {
    int warp = (blockIdx.x * blockDim.x + threadIdx.x) >> 5;
    int lane = threadIdx.x & 31;
    if (warp >= n) return;
    int b = rowptr[warp];
    int e = rowptr[warp + 1];

    // segment max
    float m = -INFINITY;
    for (int i = b + lane; i < e; i += 32) m = fmaxf(m, logitS[i]);
#pragma unroll
    for (int o = 16; o > 0; o >>= 1) m = fmaxf(m, __shfl_xor_sync(0xFFFFFFFFu, m, o));

    // segment sum of exp(l - m) * value
    float s = 0.f;
    for (int i = b + lane; i < e; i += 32) s += expf(logitS[i] - m) * valS[i];
#pragma unroll
    for (int o = 16; o > 0; o >>= 1) s += __shfl_xor_sync(0xFFFFFFFFu, s, o);
    float inv = 1.f / (s + 1e-16f);

    // weighted accumulation of h[src]
    float a0 = 0.f, a1 = 0.f, a2 = 0.f, a3 = 0.f;
    for (int i = b; i < e; i++) {
        float coef = expf(logitS[i] - m) * valS[i] * inv;
        const float* hrow = H + (size_t)srcS[i] * DIM;
        a0 = fmaf(hrow[lane], coef, a0);
        a1 = fmaf(hrow[lane + 32], coef, a1);
        a2 = fmaf(hrow[lane + 64], coef, a2);
        a3 = fmaf(hrow[lane + 96], coef, a3);
    }
    float* o = OUT + (size_t)warp * DIM;
    o[lane] = a0; o[lane + 32] = a1; o[lane + 64] = a2; o[lane + 96] = a3;
}

// ---------------------------------------------------------------------------
// Final gather with elu: out = [elu(U2[user_id]); elu(I2[item_id])]
// ---------------------------------------------------------------------------
__global__ void gather_kernel(const float* __restrict__ bufU, const float* __restrict__ bufI,
                              const int* __restrict__ uid, const int* __restrict__ iid,
                              float* __restrict__ out) {
    int idx = blockIdx.x * blockDim.x + threadIdx.x;
    const int total = 2 * BATCH * DIM;
    if (idx >= total) return;
    int j = idx & 127;
    int row = idx >> 7;
    float v;
    if (row < BATCH) v = bufU[(size_t)uid[row] * DIM + j];
    else             v = bufI[(size_t)iid[row - BATCH] * DIM + j];
    out[idx] = (v > 0.f) ? v : (expf(v) - 1.f);
}

// ---------------------------------------------------------------------------
// Host orchestration
// ---------------------------------------------------------------------------
static void build_csr(const int* src, const int* dst, const float* val, int N, int E,
                      int* rowptr, int* srcS, int* dstS, float* valS,
                      int* counts, int* cursor) {
    zero2_kernel<<<(N + 255) / 256, 256>>>(counts, cursor, N);
    hist_kernel<<<(E + 255) / 256, 256>>>(dst, counts, E);
    scan_kernel<<<1, 1024>>>(counts, rowptr, N);
    scatter_kernel<<<(E + 255) / 256, 256>>>(src, dst, val, rowptr, cursor, srcS, dstS, valS, E);
}

static void run_layer(const float* X, bool eluIn,
                      const float* W, const float* a_s, const float* a_d,
                      int N, int E,
                      const int* rowptr, const int* srcS, const int* dstS, const float* valS,
                      float* h, float* as, float* ad, float* logitS, float* OUT) {
    if (eluIn) gemm_128_kernel<true><<<(N + 63) / 64, 256>>>(X, W, h, N);
    else       gemm_128_kernel<false><<<(N + 63) / 64, 256>>>(X, W, h, N);
    alpha_kernel<<<(N + 7) / 8, 256>>>(h, a_s, a_d, as, ad, N);
    logit_kernel<<<(E + 255) / 256, 256>>>(srcS, dstS, as, ad, logitS, E);
    aggregate_kernel<<<(N + 7) / 8, 256>>>(rowptr, srcS, valS, logitS, h, OUT, N);
}

extern "C" void kernel_launch(void* const* d_in, const int* in_sizes, int n_in,
                              void* d_out, int out_size) {
    // inputs (metadata order = reference signature order)
    const int*   uedg  = (const int*)d_in[0];      // [2, E_U]
    const int*   iedg  = (const int*)d_in[1];      // [2, E_I]
    const int*   uid   = (const int*)d_in[2];      // [B]
    const int*   iid   = (const int*)d_in[3];      // [B]
    const float* uval  = (const float*)d_in[4];    // [E_U]
    const float* ival  = (const float*)d_in[5];    // [E_I]
    const float* umat  = (const float*)d_in[6];    // [N_USERS, 128]
    const float* imat  = (const float*)d_in[7];    // [N_ITEMS, 128]
    const float* W_u1  = (const float*)d_in[8];
    const float* as_u1 = (const float*)d_in[9];
    const float* ad_u1 = (const float*)d_in[10];
    const float* W_u2  = (const float*)d_in[11];
    const float* as_u2 = (const float*)d_in[12];
    const float* ad_u2 = (const float*)d_in[13];
    const float* W_i1  = (const float*)d_in[14];
    const float* as_i1 = (const float*)d_in[15];
    const float* ad_i1 = (const float*)d_in[16];
    const float* W_i2  = (const float*)d_in[17];
    const float* as_i2 = (const float*)d_in[18];
    const float* ad_i2 = (const float*)d_in[19];

    // resolve scratch symbols
    float *h, *outU1, *outU2, *outI1, *outI2, *as, *ad, *valSu, *valSi, *logitS;
    int *rpU, *rpI, *counts, *cursor, *srcSu, *dstSu, *srcSi, *dstSi;
    cudaGetSymbolAddress((void**)&h,      g_h);
    cudaGetSymbolAddress((void**)&outU1,  g_out_u1);
    cudaGetSymbolAddress((void**)&outU2,  g_out_u2);
    cudaGetSymbolAddress((void**)&outI1,  g_out_i1);
    cudaGetSymbolAddress((void**)&outI2,  g_out_i2);
    cudaGetSymbolAddress((void**)&as,     g_as);
    cudaGetSymbolAddress((void**)&ad,     g_ad);
    cudaGetSymbolAddress((void**)&rpU,    g_rowptr_u);
    cudaGetSymbolAddress((void**)&rpI,    g_rowptr_i);
    cudaGetSymbolAddress((void**)&counts, g_counts);
    cudaGetSymbolAddress((void**)&cursor, g_cursor);
    cudaGetSymbolAddress((void**)&srcSu,  g_srcS_u);
    cudaGetSymbolAddress((void**)&dstSu,  g_dstS_u);
    cudaGetSymbolAddress((void**)&valSu,  g_valS_u);
    cudaGetSymbolAddress((void**)&srcSi,  g_srcS_i);
    cudaGetSymbolAddress((void**)&dstSi,  g_dstS_i);
    cudaGetSymbolAddress((void**)&valSi,  g_valS_i);
    cudaGetSymbolAddress((void**)&logitS, g_logitS);

    // CSR by destination (graph-structure dependent only; rebuilt every launch)
    build_csr(iedg, iedg + E_I, ival, N_ITEMS, E_I, rpI, srcSi, dstSi, valSi, counts, cursor);
    build_csr(uedg, uedg + E_U, uval, N_USERS, E_U, rpU, srcSu, dstSu, valSu, counts, cursor);

    // item chain: i1 then i2
    run_layer(imat,  false, W_i1, as_i1, ad_i1, N_ITEMS, E_I, rpI, srcSi, dstSi, valSi,
              h, as, ad, logitS, outI1);
    run_layer(outI1, true,  W_i2, as_i2, ad_i2, N_ITEMS, E_I, rpI, srcSi, dstSi, valSi,
              h, as, ad, logitS, outI2);

    // user chain: u1 then u2
    run_layer(umat,  false, W_u1, as_u1, ad_u1, N_USERS, E_U, rpU, srcSu, dstSu, valSu,
              h, as, ad, logitS, outU1);
    run_layer(outU1, true,  W_u2, as_u2, ad_u2, N_USERS, E_U, rpU, srcSu, dstSu, valSu,
              h, as, ad, logitS, outU2);

    // final gather + elu
    const int total = 2 * BATCH * DIM;
    gather_kernel<<<(total + 255) / 256, 256>>>(outU2, outI2, uid, iid, (float*)d_out);
}

// round 12
// speedup vs baseline: 1.1046x; 1.1046x over previous
#include <cuda_runtime.h>
#include <math.h>

// ---------------------------------------------------------------------------
// Problem constants (fixed shapes per reference)
// ---------------------------------------------------------------------------
#define N_USERS 100000
#define N_ITEMS 50000
#define DIM     128
#define E_U     400000
#define E_I     200000
#define BATCH   4096

// ---------------------------------------------------------------------------
// Device scratch (static — no allocations allowed)
// ---------------------------------------------------------------------------
__device__ float g_h[N_USERS * DIM];
__device__ float g_out_u1[N_USERS * DIM];
__device__ float g_out_u2[N_USERS * DIM];
__device__ float g_out_i1[N_ITEMS * DIM];
__device__ float g_out_i2[N_ITEMS * DIM];
__device__ float g_as[N_USERS];
__device__ float g_ad[N_USERS];
__device__ int   g_rowptr_u[N_USERS + 1];
__device__ int   g_rowptr_i[N_ITEMS + 1];
__device__ int   g_counts[N_USERS];
__device__ int   g_cursor[N_USERS];
__device__ int   g_srcS_u[E_U];
__device__ float g_valS_u[E_U];
__device__ int   g_srcS_i[E_I];
__device__ float g_valS_i[E_I];

// ---------------------------------------------------------------------------
// Packed f32x2 helpers (sm_103a FFMA2 path — only reachable via PTX)
// ---------------------------------------------------------------------------
__device__ __forceinline__ unsigned long long f2_pack(float lo, float hi) {
    unsigned long long r;
    asm("mov.b64 %0, {%1, %2};" : "=l"(r) : "f"(lo), "f"(hi));
    return r;
}
__device__ __forceinline__ void f2_unpack(unsigned long long v, float& lo, float& hi) {
    asm("mov.b64 {%0, %1}, %2;" : "=f"(lo), "=f"(hi) : "l"(v));
}
__device__ __forceinline__ void ffma2(unsigned long long& d,
                                      unsigned long long a, unsigned long long b) {
    asm("fma.rn.f32x2 %0, %1, %2, %0;" : "+l"(d) : "l"(a), "l"(b));
}

// ---------------------------------------------------------------------------
// CSR build: histogram -> single-block scan -> scatter (src+val only)
// ---------------------------------------------------------------------------
__global__ void zero2_kernel(int* a, int* b, int n) {
    int i = blockIdx.x * blockDim.x + threadIdx.x;
    if (i < n) { a[i] = 0; b[i] = 0; }
}

__global__ void hist_kernel(const int* __restrict__ dst, int* counts, int E) {
    int e = blockIdx.x * blockDim.x + threadIdx.x;
    if (e < E) atomicAdd(&counts[dst[e]], 1);
}

__global__ void scan_kernel(const int* __restrict__ counts, int* __restrict__ rowptr, int n) {
    __shared__ int ssum[1024];
    int t = threadIdx.x;
    int chunk = (n + 1023) / 1024;
    int lo = t * chunk;
    int hi = min(lo + chunk, n);
    int s = 0;
    for (int i = lo; i < hi; i++) s += counts[i];
    ssum[t] = s;
    __syncthreads();
    for (int o = 1; o < 1024; o <<= 1) {
        int v = (t >= o) ? ssum[t - o] : 0;
        __syncthreads();
        ssum[t] += v;
        __syncthreads();
    }
    int run = (t > 0) ? ssum[t - 1] : 0;
    for (int i = lo; i < hi; i++) { rowptr[i] = run; run += counts[i]; }
    if (t == 0) rowptr[n] = ssum[1023];
}

__global__ void scatter_kernel(const int* __restrict__ src, const int* __restrict__ dst,
                               const float* __restrict__ val,
                               const int* __restrict__ rowptr, int* cursor,
                               int* srcS, float* valS, int E) {
    int e = blockIdx.x * blockDim.x + threadIdx.x;
    if (e >= E) return;
    int d = dst[e];
    int pos = rowptr[d] + atomicAdd(&cursor[d], 1);
    srcS[pos] = src[e];
    valS[pos] = val[e];
}

// ---------------------------------------------------------------------------
// GEMM + fused alpha: H = elu?(X) @ W ; as[n]=H[n]·a_src ; ad[n]=H[n]·a_dst
// Block 256 threads, tile 64 rows x 128 cols, K chunked by 32.
// Each thread: 4 rows x 4 col-PAIRS, accumulated with packed fma.rn.f32x2.
// ---------------------------------------------------------------------------
template <bool ELU_IN>
__global__ void gemm_alpha_kernel(const float* __restrict__ X, const float* __restrict__ W,
                                  const float* __restrict__ a_src, const float* __restrict__ a_dst,
                                  float* __restrict__ H,
                                  float* __restrict__ as, float* __restrict__ ad, int n) {
    __shared__ float xs[64][33];
    __shared__ float ws[32][128];
    __shared__ float s_av[2][128];
    int tid = threadIdx.x;
    int tx = tid & 15;          // column-pair group: pairs at cols tx*2 + 32*j
    int ty = tid >> 4;          // row group: rows ty + 16*i
    int row0 = blockIdx.x * 64;

    if (tid < 128) { s_av[0][tid] = a_src[tid]; s_av[1][tid] = a_dst[tid]; }

    unsigned long long acc[4][4];
#pragma unroll
    for (int i = 0; i < 4; i++)
#pragma unroll
        for (int j = 0; j < 4; j++) acc[i][j] = 0ull;   // bits of {0.f, 0.f}

    for (int k0 = 0; k0 < DIM; k0 += 32) {
        for (int i = tid; i < 64 * 32; i += 256) {
            int r = i >> 5, c = i & 31;
            int gr = row0 + r;
            float v = (gr < n) ? X[(size_t)gr * DIM + k0 + c] : 0.f;
            if (ELU_IN) v = (v > 0.f) ? v : (expf(v) - 1.f);
            xs[r][c] = v;
        }
        for (int i = tid; i < 32 * 128; i += 256) {
            int r = i >> 7, c = i & 127;
            ws[r][c] = W[(size_t)(k0 + r) * DIM + c];
        }
        __syncthreads();
#pragma unroll 8
        for (int kk = 0; kk < 32; kk++) {
            unsigned long long av[4], bv[4];
#pragma unroll
            for (int i = 0; i < 4; i++) {
                float a = xs[ty + 16 * i][kk];
                av[i] = f2_pack(a, a);
            }
#pragma unroll
            for (int j = 0; j < 4; j++) {
                float2 b = *(const float2*)&ws[kk][tx * 2 + 32 * j];
                bv[j] = f2_pack(b.x, b.y);
            }
#pragma unroll
            for (int i = 0; i < 4; i++)
#pragma unroll
                for (int j = 0; j < 4; j++) ffma2(acc[i][j], av[i], bv[j]);
        }
        __syncthreads();
    }

    // epilogue: store H and reduce per-row dots with a_src / a_dst
#pragma unroll
    for (int i = 0; i < 4; i++) {
        int gr = row0 + ty + 16 * i;
        float ps = 0.f, pd = 0.f;
        if (gr < n) {
#pragma unroll
            for (int j = 0; j < 4; j++) {
                float lo, hi;
                f2_unpack(acc[i][j], lo, hi);
                int c = tx * 2 + 32 * j;
                float2 st; st.x = lo; st.y = hi;
                *(float2*)&H[(size_t)gr * DIM + c] = st;
                ps = fmaf(lo, s_av[0][c], fmaf(hi, s_av[0][c + 1], ps));
                pd = fmaf(lo, s_av[1][c], fmaf(hi, s_av[1][c + 1], pd));
            }
        }
        // reduce across the 16-thread column group (stays within half-warp)
#pragma unroll
        for (int o = 8; o > 0; o >>= 1) {
            ps += __shfl_xor_sync(0xFFFFFFFFu, ps, o);
            pd += __shfl_xor_sync(0xFFFFFFFFu, pd, o);
        }
        if (tx == 0 && gr < n) { as[gr] = ps; ad[gr] = pd; }
    }
}

// ---------------------------------------------------------------------------
// Fused neighbor softmax + aggregation: one warp per destination node.
// Logits recomputed in-warp (dst == warp id -> ad is a scalar); single pass
// accumulates unnormalized sum(w*h) and sum(w), normalized at the end.
// Serial loop is software-pipelined: next edge's src/val/as loads are issued
// before the current edge's FMA chain consumes its h row.
// ---------------------------------------------------------------------------
__global__ void aggregate_kernel(const int* __restrict__ rowptr, const int* __restrict__ srcS,
                                 const float* __restrict__ valS,
                                 const float* __restrict__ as, const float* __restrict__ ad,
                                 const float* __restrict__ H, float* __restrict__ OUT, int n) {
    int warp = (blockIdx.x * blockDim.x + threadIdx.x) >> 5;
    int lane = threadIdx.x & 31;
    if (warp >= n) return;
    int b = rowptr[warp];
    int e = rowptr[warp + 1];
    float adv = ad[warp];

    // segment max of leaky_relu(as[src] + ad[dst])
    float m = -INFINITY;
    for (int i = b + lane; i < e; i += 32) {
        float l = as[srcS[i]] + adv;
        l = (l >= 0.f) ? l : 0.2f * l;
        m = fmaxf(m, l);
    }
#pragma unroll
    for (int o = 16; o > 0; o >>= 1) m = fmaxf(m, __shfl_xor_sync(0xFFFFFFFFu, m, o));

    // single pass: unnormalized weighted feature sum + denominator (pipelined)
    float4 acc = make_float4(0.f, 0.f, 0.f, 0.f);
    float s = 0.f;
    if (b < e) {
        int   src_c = __ldg(&srcS[b]);
        float val_c = __ldg(&valS[b]);
        float as_c  = __ldg(&as[src_c]);
        for (int i = b; i < e; i++) {
            int   src_n = 0; float val_n = 0.f, as_n = 0.f;
            if (i + 1 < e) {
                src_n = __ldg(&srcS[i + 1]);
                val_n = __ldg(&valS[i + 1]);
                as_n  = __ldg(&as[src_n]);
            }
            float4 hv = ((const float4*)(H + (size_t)src_c * DIM))[lane];
            float l = as_c + adv;
            l = (l >= 0.f) ? l : 0.2f * l;
            float w = expf(l - m) * val_c;
            s += w;
            acc.x = fmaf(w, hv.x, acc.x);
            acc.y = fmaf(w, hv.y, acc.y);
            acc.z = fmaf(w, hv.z, acc.z);
            acc.w = fmaf(w, hv.w, acc.w);
            src_c = src_n; val_c = val_n; as_c = as_n;
        }
    }
    float inv = 1.f / (s + 1e-16f);
    acc.x *= inv; acc.y *= inv; acc.z *= inv; acc.w *= inv;
    ((float4*)(OUT + (size_t)warp * DIM))[lane] = acc;
}

// ---------------------------------------------------------------------------
// Final gather with elu
// ---------------------------------------------------------------------------
__global__ void gather_kernel(const float* __restrict__ bufU, const float* __restrict__ bufI,
                              const int* __restrict__ uid, const int* __restrict__ iid,
                              float* __restrict__ out) {
    int idx = blockIdx.x * blockDim.x + threadIdx.x;
    const int total = 2 * BATCH * DIM;
    if (idx >= total) return;
    int j = idx & 127;
    int row = idx >> 7;
    float v;
    if (row < BATCH) v = bufU[(size_t)uid[row] * DIM + j];
    else             v = bufI[(size_t)iid[row - BATCH] * DIM + j];
    out[idx] = (v > 0.f) ? v : (expf(v) - 1.f);
}

// ---------------------------------------------------------------------------
// Host orchestration
// ---------------------------------------------------------------------------
static void build_csr(const int* src, const int* dst, const float* val, int N, int E,
                      int* rowptr, int* srcS, float* valS, int* counts, int* cursor) {
    zero2_kernel<<<(N + 255) / 256, 256>>>(counts, cursor, N);
    hist_kernel<<<(E + 255) / 256, 256>>>(dst, counts, E);
    scan_kernel<<<1, 1024>>>(counts, rowptr, N);
    scatter_kernel<<<(E + 255) / 256, 256>>>(src, dst, val, rowptr, cursor, srcS, valS, E);
}

static void run_layer(const float* X, bool eluIn,
                      const float* W, const float* a_s, const float* a_d,
                      int N, int E,
                      const int* rowptr, const int* srcS, const float* valS,
                      float* h, float* as, float* ad, float* OUT) {
    if (eluIn) gemm_alpha_kernel<true><<<(N + 63) / 64, 256>>>(X, W, a_s, a_d, h, as, ad, N);
    else       gemm_alpha_kernel<false><<<(N + 63) / 64, 256>>>(X, W, a_s, a_d, h, as, ad, N);
    aggregate_kernel<<<(N + 7) / 8, 256>>>(rowptr, srcS, valS, as, ad, h, OUT, N);
}

extern "C" void kernel_launch(void* const* d_in, const int* in_sizes, int n_in,
                              void* d_out, int out_size) {
    const int*   uedg  = (const int*)d_in[0];
    const int*   iedg  = (const int*)d_in[1];
    const int*   uid   = (const int*)d_in[2];
    const int*   iid   = (const int*)d_in[3];
    const float* uval  = (const float*)d_in[4];
    const float* ival  = (const float*)d_in[5];
    const float* umat  = (const float*)d_in[6];
    const float* imat  = (const float*)d_in[7];
    const float* W_u1  = (const float*)d_in[8];
    const float* as_u1 = (const float*)d_in[9];
    const float* ad_u1 = (const float*)d_in[10];
    const float* W_u2  = (const float*)d_in[11];
    const float* as_u2 = (const float*)d_in[12];
    const float* ad_u2 = (const float*)d_in[13];
    const float* W_i1  = (const float*)d_in[14];
    const float* as_i1 = (const float*)d_in[15];
    const float* ad_i1 = (const float*)d_in[16];
    const float* W_i2  = (const float*)d_in[17];
    const float* as_i2 = (const float*)d_in[18];
    const float* ad_i2 = (const float*)d_in[19];

    float *h, *outU1, *outU2, *outI1, *outI2, *as, *ad, *valSu, *valSi;
    int *rpU, *rpI, *counts, *cursor, *srcSu, *srcSi;
    cudaGetSymbolAddress((void**)&h,      g_h);
    cudaGetSymbolAddress((void**)&outU1,  g_out_u1);
    cudaGetSymbolAddress((void**)&outU2,  g_out_u2);
    cudaGetSymbolAddress((void**)&outI1,  g_out_i1);
    cudaGetSymbolAddress((void**)&outI2,  g_out_i2);
    cudaGetSymbolAddress((void**)&as,     g_as);
    cudaGetSymbolAddress((void**)&ad,     g_ad);
    cudaGetSymbolAddress((void**)&rpU,    g_rowptr_u);
    cudaGetSymbolAddress((void**)&rpI,    g_rowptr_i);
    cudaGetSymbolAddress((void**)&counts, g_counts);
    cudaGetSymbolAddress((void**)&cursor, g_cursor);
    cudaGetSymbolAddress((void**)&srcSu,  g_srcS_u);
    cudaGetSymbolAddress((void**)&valSu,  g_valS_u);
    cudaGetSymbolAddress((void**)&srcSi,  g_srcS_i);
    cudaGetSymbolAddress((void**)&valSi,  g_valS_i);

    build_csr(iedg, iedg + E_I, ival, N_ITEMS, E_I, rpI, srcSi, valSi, counts, cursor);
    build_csr(uedg, uedg + E_U, uval, N_USERS, E_U, rpU, srcSu, valSu, counts, cursor);

    // item chain
    run_layer(imat,  false, W_i1, as_i1, ad_i1, N_ITEMS, E_I, rpI, srcSi, valSi, h, as, ad, outI1);
    run_layer(outI1, true,  W_i2, as_i2, ad_i2, N_ITEMS, E_I, rpI, srcSi, valSi, h, as, ad, outI2);

    // user chain
    run_layer(umat,  false, W_u1, as_u1, ad_u1, N_USERS, E_U, rpU, srcSu, valSu, h, as, ad, outU1);
    run_layer(outU1, true,  W_u2, as_u2, ad_u2, N_USERS, E_U, rpU, srcSu, valSu, h, as, ad, outU2);

    const int total = 2 * BATCH * DIM;
    gather_kernel<<<(total + 255) / 256, 256>>>(outU2, outI2, uid, iid, (float*)d_out);
}

// round 16
// speedup vs baseline: 1.1523x; 1.0431x over previous
#include <cuda_runtime.h>
#include <math.h>

// ---------------------------------------------------------------------------
// Problem constants (fixed shapes per reference)
// ---------------------------------------------------------------------------
#define N_USERS 100000
#define N_ITEMS 50000
#define DIM     128
#define E_U     400000
#define E_I     200000
#define BATCH   4096

// ---------------------------------------------------------------------------
// Device scratch (static — no allocations allowed)
// ---------------------------------------------------------------------------
__device__ float g_h[N_USERS * DIM];
__device__ float g_out_u1[N_USERS * DIM];
__device__ float g_out_u2[N_USERS * DIM];
__device__ float g_out_i1[N_ITEMS * DIM];
__device__ float g_out_i2[N_ITEMS * DIM];
__device__ float g_as[N_USERS];
__device__ float g_ad[N_USERS];
__device__ int   g_rowptr_u[N_USERS + 1];
__device__ int   g_rowptr_i[N_ITEMS + 1];
__device__ int   g_counts[N_USERS];
__device__ int   g_cursor[N_USERS];
__device__ int   g_srcS_u[E_U];
__device__ float g_valS_u[E_U];
__device__ int   g_srcS_i[E_I];
__device__ float g_valS_i[E_I];

// ---------------------------------------------------------------------------
// Packed f32x2 helpers (sm_103a FFMA2 path — only reachable via PTX)
// ---------------------------------------------------------------------------
__device__ __forceinline__ unsigned long long f2_pack(float lo, float hi) {
    unsigned long long r;
    asm("mov.b64 %0, {%1, %2};" : "=l"(r) : "f"(lo), "f"(hi));
    return r;
}
__device__ __forceinline__ void f2_unpack(unsigned long long v, float& lo, float& hi) {
    asm("mov.b64 {%0, %1}, %2;" : "=f"(lo), "=f"(hi) : "l"(v));
}
__device__ __forceinline__ void ffma2(unsigned long long& d,
                                      unsigned long long a, unsigned long long b) {
    asm("fma.rn.f32x2 %0, %1, %2, %0;" : "+l"(d) : "l"(a), "l"(b));
}

// ---------------------------------------------------------------------------
// CSR build: histogram -> single-block scan -> scatter (src+val only)
// ---------------------------------------------------------------------------
__global__ void zero2_kernel(int* a, int* b, int n) {
    int i = blockIdx.x * blockDim.x + threadIdx.x;
    if (i < n) { a[i] = 0; b[i] = 0; }
}

__global__ void hist_kernel(const int* __restrict__ dst, int* counts, int E) {
    int e = blockIdx.x * blockDim.x + threadIdx.x;
    if (e < E) atomicAdd(&counts[dst[e]], 1);
}

__global__ void scan_kernel(const int* __restrict__ counts, int* __restrict__ rowptr, int n) {
    __shared__ int ssum[1024];
    int t = threadIdx.x;
    int chunk = (n + 1023) / 1024;
    int lo = t * chunk;
    int hi = min(lo + chunk, n);
    int s = 0;
    for (int i = lo; i < hi; i++) s += counts[i];
    ssum[t] = s;
    __syncthreads();
    for (int o = 1; o < 1024; o <<= 1) {
        int v = (t >= o) ? ssum[t - o] : 0;
        __syncthreads();
        ssum[t] += v;
        __syncthreads();
    }
    int run = (t > 0) ? ssum[t - 1] : 0;
    for (int i = lo; i < hi; i++) { rowptr[i] = run; run += counts[i]; }
    if (t == 0) rowptr[n] = ssum[1023];
}

__global__ void scatter_kernel(const int* __restrict__ src, const int* __restrict__ dst,
                               const float* __restrict__ val,
                               const int* __restrict__ rowptr, int* cursor,
                               int* srcS, float* valS, int E) {
    int e = blockIdx.x * blockDim.x + threadIdx.x;
    if (e >= E) return;
    int d = dst[e];
    int pos = rowptr[d] + atomicAdd(&cursor[d], 1);
    srcS[pos] = src[e];
    valS[pos] = val[e];
}

// ---------------------------------------------------------------------------
// GEMM + fused alpha: H = elu?(X) @ W ; as[n]=H[n]·a_src ; ad[n]=H[n]·a_dst
// (unchanged from R12 — its share gets measured this round via launch order)
// ---------------------------------------------------------------------------
template <bool ELU_IN>
__global__ void gemm_alpha_kernel(const float* __restrict__ X, const float* __restrict__ W,
                                  const float* __restrict__ a_src, const float* __restrict__ a_dst,
                                  float* __restrict__ H,
                                  float* __restrict__ as, float* __restrict__ ad, int n) {
    __shared__ float xs[64][33];
    __shared__ float ws[32][128];
    __shared__ float s_av[2][128];
    int tid = threadIdx.x;
    int tx = tid & 15;
    int ty = tid >> 4;
    int row0 = blockIdx.x * 64;

    if (tid < 128) { s_av[0][tid] = a_src[tid]; s_av[1][tid] = a_dst[tid]; }

    unsigned long long acc[4][4];
#pragma unroll
    for (int i = 0; i < 4; i++)
#pragma unroll
        for (int j = 0; j < 4; j++) acc[i][j] = 0ull;

    for (int k0 = 0; k0 < DIM; k0 += 32) {
        for (int i = tid; i < 64 * 32; i += 256) {
            int r = i >> 5, c = i & 31;
            int gr = row0 + r;
            float v = (gr < n) ? X[(size_t)gr * DIM + k0 + c] : 0.f;
            if (ELU_IN) v = (v > 0.f) ? v : (expf(v) - 1.f);
            xs[r][c] = v;
        }
        for (int i = tid; i < 32 * 128; i += 256) {
            int r = i >> 7, c = i & 127;
            ws[r][c] = W[(size_t)(k0 + r) * DIM + c];
        }
        __syncthreads();
#pragma unroll 8
        for (int kk = 0; kk < 32; kk++) {
            unsigned long long av[4], bv[4];
#pragma unroll
            for (int i = 0; i < 4; i++) {
                float a = xs[ty + 16 * i][kk];
                av[i] = f2_pack(a, a);
            }
#pragma unroll
            for (int j = 0; j < 4; j++) {
                float2 b = *(const float2*)&ws[kk][tx * 2 + 32 * j];
                bv[j] = f2_pack(b.x, b.y);
            }
#pragma unroll
            for (int i = 0; i < 4; i++)
#pragma unroll
                for (int j = 0; j < 4; j++) ffma2(acc[i][j], av[i], bv[j]);
        }
        __syncthreads();
    }

#pragma unroll
    for (int i = 0; i < 4; i++) {
        int gr = row0 + ty + 16 * i;
        float ps = 0.f, pd = 0.f;
        if (gr < n) {
#pragma unroll
            for (int j = 0; j < 4; j++) {
                float lo, hi;
                f2_unpack(acc[i][j], lo, hi);
                int c = tx * 2 + 32 * j;
                float2 st; st.x = lo; st.y = hi;
                *(float2*)&H[(size_t)gr * DIM + c] = st;
                ps = fmaf(lo, s_av[0][c], fmaf(hi, s_av[0][c + 1], ps));
                pd = fmaf(lo, s_av[1][c], fmaf(hi, s_av[1][c + 1], pd));
            }
        }
#pragma unroll
        for (int o = 8; o > 0; o >>= 1) {
            ps += __shfl_xor_sync(0xFFFFFFFFu, ps, o);
            pd += __shfl_xor_sync(0xFFFFFFFFu, pd, o);
        }
        if (tx == 0 && gr < n) { as[gr] = ps; ad[gr] = pd; }
    }
}

// ---------------------------------------------------------------------------
// Fused softmax + aggregation v2: one warp per destination node.
// Edge metadata is loaded LANE-PARALLEL (no serial chained loads); the
// per-edge (src, w) pairs are broadcast via shfl (register traffic only);
// H-row float4 loads across edges are independent -> full MLP; dual
// accumulators break the FMA dependency chain. Chunks of 32 handle d > 32.
// ---------------------------------------------------------------------------
__global__ void aggregate_kernel(const int* __restrict__ rowptr, const int* __restrict__ srcS,
                                 const float* __restrict__ valS,
                                 const float* __restrict__ as, const float* __restrict__ ad,
                                 const float* __restrict__ H, float* __restrict__ OUT, int n) {
    int warp = (blockIdx.x * blockDim.x + threadIdx.x) >> 5;
    int lane = threadIdx.x & 31;
    if (warp >= n) return;
    int b = rowptr[warp];
    int e = rowptr[warp + 1];
    float adv = ad[warp];

    // pass 1: segment max of leaky_relu(as[src] + ad[dst]) — lane-parallel
    float m = -INFINITY;
    for (int i = b + lane; i < e; i += 32) {
        float l = as[srcS[i]] + adv;
        l = (l >= 0.f) ? l : 0.2f * l;
        m = fmaxf(m, l);
    }
#pragma unroll
    for (int o = 16; o > 0; o >>= 1) m = fmaxf(m, __shfl_xor_sync(0xFFFFFFFFu, m, o));

    // pass 2: lane-parallel weights per 32-edge chunk, shfl-broadcast accumulate
    float4 acc0 = make_float4(0.f, 0.f, 0.f, 0.f);
    float4 acc1 = make_float4(0.f, 0.f, 0.f, 0.f);
    float s_part = 0.f;
    for (int base = b; base < e; base += 32) {
        int cnt = min(32, e - base);
        int   src_l = 0;
        float w_l = 0.f;
        if (lane < cnt) {
            int idx = base + lane;
            src_l = __ldg(&srcS[idx]);
            float l = __ldg(&as[src_l]) + adv;
            l = (l >= 0.f) ? l : 0.2f * l;
            w_l = expf(l - m) * __ldg(&valS[idx]);
        }
        s_part += w_l;
        int j = 0;
        for (; j + 1 < cnt; j += 2) {
            int   s0 = __shfl_sync(0xFFFFFFFFu, src_l, j);
            float w0 = __shfl_sync(0xFFFFFFFFu, w_l,  j);
            int   s1 = __shfl_sync(0xFFFFFFFFu, src_l, j + 1);
            float w1 = __shfl_sync(0xFFFFFFFFu, w_l,  j + 1);
            float4 h0 = ((const float4*)(H + (size_t)s0 * DIM))[lane];
            float4 h1 = ((const float4*)(H + (size_t)s1 * DIM))[lane];
            acc0.x = fmaf(w0, h0.x, acc0.x);
            acc0.y = fmaf(w0, h0.y, acc0.y);
            acc0.z = fmaf(w0, h0.z, acc0.z);
            acc0.w = fmaf(w0, h0.w, acc0.w);
            acc1.x = fmaf(w1, h1.x, acc1.x);
            acc1.y = fmaf(w1, h1.y, acc1.y);
            acc1.z = fmaf(w1, h1.z, acc1.z);
            acc1.w = fmaf(w1, h1.w, acc1.w);
        }
        if (j < cnt) {
            int   s0 = __shfl_sync(0xFFFFFFFFu, src_l, j);
            float w0 = __shfl_sync(0xFFFFFFFFu, w_l,  j);
            float4 h0 = ((const float4*)(H + (size_t)s0 * DIM))[lane];
            acc0.x = fmaf(w0, h0.x, acc0.x);
            acc0.y = fmaf(w0, h0.y, acc0.y);
            acc0.z = fmaf(w0, h0.z, acc0.z);
            acc0.w = fmaf(w0, h0.w, acc0.w);
        }
    }
    float s = s_part;
#pragma unroll
    for (int o = 16; o > 0; o >>= 1) s += __shfl_xor_sync(0xFFFFFFFFu, s, o);
    float inv = 1.f / (s + 1e-16f);
    float4 r;
    r.x = (acc0.x + acc1.x) * inv;
    r.y = (acc0.y + acc1.y) * inv;
    r.z = (acc0.z + acc1.z) * inv;
    r.w = (acc0.w + acc1.w) * inv;
    ((float4*)(OUT + (size_t)warp * DIM))[lane] = r;
}

// ---------------------------------------------------------------------------
// Final gather with elu
// ---------------------------------------------------------------------------
__global__ void gather_kernel(const float* __restrict__ bufU, const float* __restrict__ bufI,
                              const int* __restrict__ uid, const int* __restrict__ iid,
                              float* __restrict__ out) {
    int idx = blockIdx.x * blockDim.x + threadIdx.x;
    const int total = 2 * BATCH * DIM;
    if (idx >= total) return;
    int j = idx & 127;
    int row = idx >> 7;
    float v;
    if (row < BATCH) v = bufU[(size_t)uid[row] * DIM + j];
    else             v = bufI[(size_t)iid[row - BATCH] * DIM + j];
    out[idx] = (v > 0.f) ? v : (expf(v) - 1.f);
}

// ---------------------------------------------------------------------------
// Host orchestration
// NOTE: launch ORDER is engineered so the 4th launch (the slot ncu's
// -s/-c capture has hit in both successful profiles) is the LARGEST kernel
// (user-layer-1 GEMM, grid 1563) instead of a 8-µs scatter. gemm_u1 has no
// dependency on the user CSR, so inserting it between scan_u and scatter_u
// is dependency-safe and perf-neutral.
// ---------------------------------------------------------------------------
extern "C" void kernel_launch(void* const* d_in, const int* in_sizes, int n_in,
                              void* d_out, int out_size) {
    const int*   uedg  = (const int*)d_in[0];
    const int*   iedg  = (const int*)d_in[1];
    const int*   uid   = (const int*)d_in[2];
    const int*   iid   = (const int*)d_in[3];
    const float* uval  = (const float*)d_in[4];
    const float* ival  = (const float*)d_in[5];
    const float* umat  = (const float*)d_in[6];
    const float* imat  = (const float*)d_in[7];
    const float* W_u1  = (const float*)d_in[8];
    const float* as_u1 = (const float*)d_in[9];
    const float* ad_u1 = (const float*)d_in[10];
    const float* W_u2  = (const float*)d_in[11];
    const float* as_u2 = (const float*)d_in[12];
    const float* ad_u2 = (const float*)d_in[13];
    const float* W_i1  = (const float*)d_in[14];
    const float* as_i1 = (const float*)d_in[15];
    const float* ad_i1 = (const float*)d_in[16];
    const float* W_i2  = (const float*)d_in[17];
    const float* as_i2 = (const float*)d_in[18];
    const float* ad_i2 = (const float*)d_in[19];

    float *h, *outU1, *outU2, *outI1, *outI2, *as, *ad, *valSu, *valSi;
    int *rpU, *rpI, *counts, *cursor, *srcSu, *srcSi;
    cudaGetSymbolAddress((void**)&h,      g_h);
    cudaGetSymbolAddress((void**)&outU1,  g_out_u1);
    cudaGetSymbolAddress((void**)&outU2,  g_out_u2);
    cudaGetSymbolAddress((void**)&outI1,  g_out_i1);
    cudaGetSymbolAddress((void**)&outI2,  g_out_i2);
    cudaGetSymbolAddress((void**)&as,     g_as);
    cudaGetSymbolAddress((void**)&ad,     g_ad);
    cudaGetSymbolAddress((void**)&rpU,    g_rowptr_u);
    cudaGetSymbolAddress((void**)&rpI,    g_rowptr_i);
    cudaGetSymbolAddress((void**)&counts, g_counts);
    cudaGetSymbolAddress((void**)&cursor, g_cursor);
    cudaGetSymbolAddress((void**)&srcSu,  g_srcS_u);
    cudaGetSymbolAddress((void**)&valSu,  g_valS_u);
    cudaGetSymbolAddress((void**)&srcSi,  g_srcS_i);
    cudaGetSymbolAddress((void**)&valSi,  g_valS_i);

    // --- user chain first; gemm_u1 occupies the profiled (4th) launch slot ---
    zero2_kernel<<<(N_USERS + 255) / 256, 256>>>(counts, cursor, N_USERS);                 // 0
    hist_kernel<<<(E_U + 255) / 256, 256>>>(uedg + E_U, counts, E_U);                      // 1
    scan_kernel<<<1, 1024>>>(counts, rpU, N_USERS);                                        // 2
    gemm_alpha_kernel<false><<<(N_USERS + 63) / 64, 256>>>(umat, W_u1, as_u1, ad_u1,
                                                           h, as, ad, N_USERS);            // 3 (PROFILED)
    scatter_kernel<<<(E_U + 255) / 256, 256>>>(uedg, uedg + E_U, uval, rpU, cursor,
                                               srcSu, valSu, E_U);                         // 4
    aggregate_kernel<<<(N_USERS + 7) / 8, 256>>>(rpU, srcSu, valSu, as, ad, h,
                                                 outU1, N_USERS);                          // 5
    gemm_alpha_kernel<true><<<(N_USERS + 63) / 64, 256>>>(outU1, W_u2, as_u2, ad_u2,
                                                          h, as, ad, N_USERS);             // 6
    aggregate_kernel<<<(N_USERS + 7) / 8, 256>>>(rpU, srcSu, valSu, as, ad, h,
                                                 outU2, N_USERS);                          // 7

    // --- item chain ---
    zero2_kernel<<<(N_ITEMS + 255) / 256, 256>>>(counts, cursor, N_ITEMS);                 // 8
    hist_kernel<<<(E_I + 255) / 256, 256>>>(iedg + E_I, counts, E_I);                      // 9
    scan_kernel<<<1, 1024>>>(counts, rpI, N_ITEMS);                                        // 10
    scatter_kernel<<<(E_I + 255) / 256, 256>>>(iedg, iedg + E_I, ival, rpI, cursor,
                                               srcSi, valSi, E_I);                         // 11
    gemm_alpha_kernel<false><<<(N_ITEMS + 63) / 64, 256>>>(imat, W_i1, as_i1, ad_i1,
                                                           h, as, ad, N_ITEMS);            // 12
    aggregate_kernel<<<(N_ITEMS + 7) / 8, 256>>>(rpI, srcSi, valSi, as, ad, h,
                                                 outI1, N_ITEMS);                          // 13
    gemm_alpha_kernel<true><<<(N_ITEMS + 63) / 64, 256>>>(outI1, W_i2, as_i2, ad_i2,
                                                          h, as, ad, N_ITEMS);             // 14
    aggregate_kernel<<<(N_ITEMS + 7) / 8, 256>>>(rpI, srcSi, valSi, as, ad, h,
                                                 outI2, N_ITEMS);                          // 15

    const int total = 2 * BATCH * DIM;
    gather_kernel<<<(total + 255) / 256, 256>>>(outU2, outI2, uid, iid, (float*)d_out);    // 16
}